// round 17
// baseline (speedup 1.0000x reference)
#include <cuda_runtime.h>

// EOQLinear int4-GEMV, N=K=8192, qblock=128. x/scales/out fp32 (harness
// promotes fp16). packed_w int32: lo nibble -> even k, hi -> odd k, offset-8.
// HBM-bound: 128MB of W read once per launch.
//
// R14: the 64-warp experiment. All prior designs ran <=32 warps/SM; this one
// runs TPB=1024 with launch_bounds(1024,2) = 2048 threads = 64 warps/SM via a
// <=32-reg layout: each thread owns ONE int4 position (xr = 8 floats), no
// cross-row accumulators (each row's scaled partial goes straight to smem).
// Persistent 296 CTAs (one balanced wave), chunks of 8 rows, ping-pong red
// buffers so warps 0-7 reduce chunk c while warps 8-31 stream chunk c+1;
// one __syncthreads per 8 rows.

constexpr int TPB     = 1024;
constexpr int CHUNK   = 8;        // rows per chunk
constexpr int WORKERS = 296;      // 148 SMs x 2 CTAs, single wave
constexpr int QBLK    = 64;       // quant blocks per row
constexpr int I4ROW   = 1024;     // int4 (16B) per row
constexpr int SMEM_BYTES = 2 * CHUNK * TPB * 4;   // ping-pong partial buffers

// (w & 0xF) | 0x4B000000 is exactly float(2^23 + lo); subtract 2^23+8 -> exact lo-8.
__device__ __forceinline__ float dec_lo(int w) {
    return __int_as_float((w & 0xF) | 0x4B000000) - 8388616.0f;
}
__device__ __forceinline__ float dec_hi(int w) {
    return __int_as_float(((w >> 4) & 0xF) | 0x4B000000) - 8388616.0f;
}

__global__ __launch_bounds__(TPB, 2)
void q4_gemv_kernel(const float* __restrict__ x,       // [8192]
                    const int4*  __restrict__ wq,      // [8192, 1024] int4 view
                    const float* __restrict__ scales,  // [8192, 64]
                    float* __restrict__ out,           // [8192]
                    int n_rows)
{
    extern __shared__ float red[];   // [2][CHUNK][TPB]

    const int t  = threadIdx.x;      // this thread's int4 index within every row
    const int qb = t >> 4;           // its qblock (16 int4 per qblock)

    // ---- Fixed x slice: 8 floats, loaded once per CTA. ----
    const float4 xa = *reinterpret_cast<const float4*>(x + t * 8);
    const float4 xb = *reinterpret_cast<const float4*>(x + t * 8 + 4);

    // ---- Balanced contiguous row range for this CTA (27 or 28 rows). ----
    const int cta  = blockIdx.x;
    const int rbeg = (int)(((long long)n_rows * cta) / WORKERS);
    const int rend = (int)(((long long)n_rows * (cta + 1)) / WORKERS);
    const int nch  = (rend - rbeg + CHUNK - 1) / CHUNK;

    const int wid = t >> 5, lane = t & 31;

    int prev_r0 = 0, prev_nr = 0;

    for (int c = 0; c <= nch; c++) {
        // ---- Reduce previous chunk (warps 0-7), overlapped with streaming. ----
        if (c > 0 && wid < prev_nr) {
            const float* rp = red + ((c - 1) & 1) * (CHUNK * TPB) + wid * TPB;
            float v = 0.0f;
#pragma unroll
            for (int k = 0; k < TPB / 32; k++) v += rp[lane + 32 * k];
#pragma unroll
            for (int o = 16; o > 0; o >>= 1) v += __shfl_xor_sync(0xFFFFFFFFu, v, o);
            if (lane == 0) out[prev_r0 + wid] = v;
        }

        // ---- Stream this chunk's rows (all warps; 8-31 start immediately). ----
        if (c < nch) {
            const int r0 = rbeg + c * CHUNK;
            const int nr = min(CHUNK, rend - r0);
            float* rb = red + (c & 1) * (CHUNK * TPB);
#pragma unroll
            for (int r = 0; r < CHUNK; r++) {
                if (r >= nr) break;
                const int row = r0 + r;
                const int4  wv = __ldcs(wq + (long)row * I4ROW + t);     // 512B/warp, coalesced
                const float sc = __ldg(scales + (long)row * QBLK + qb);  // broadcast, L1-hot
                float p = 0.0f;
                p = fmaf(dec_lo(wv.x), xa.x, p);
                p = fmaf(dec_hi(wv.x), xa.y, p);
                p = fmaf(dec_lo(wv.y), xa.z, p);
                p = fmaf(dec_hi(wv.y), xa.w, p);
                p = fmaf(dec_lo(wv.z), xb.x, p);
                p = fmaf(dec_hi(wv.z), xb.y, p);
                p = fmaf(dec_lo(wv.w), xb.z, p);
                p = fmaf(dec_hi(wv.w), xb.w, p);
                rb[r * TPB + t] = p * sc;   // factored-scale partial, exact per qblock slice
            }
            prev_r0 = r0; prev_nr = nr;
        }
        __syncthreads();   // chunk stores done; previous buffer free for reuse
    }
}

extern "C" void kernel_launch(void* const* d_in, const int* in_sizes, int n_in,
                              void* d_out, int out_size) {
    const float* x      = (const float*)d_in[0];
    const int4*  wq     = (const int4*)d_in[1];
    const float* scales = (const float*)d_in[2];
    // d_in[3] = qblock_size (128), compile-time constant here.
    float* out = (float*)d_out;

    cudaFuncSetAttribute(q4_gemv_kernel,
                         cudaFuncAttributeMaxDynamicSharedMemorySize, SMEM_BYTES);

    const int n_rows = out_size;  // 8192
    q4_gemv_kernel<<<WORKERS, TPB, SMEM_BYTES>>>(x, wq, scales, out, n_rows);
}